// round 8
// baseline (speedup 1.0000x reference)
#include <cuda_runtime.h>
#include <cuda_fp16.h>
#include <cstdint>
#include <math.h>

#define S_LEN    2048
#define D_MODEL  1024
#define N_HEADS  16
#define D_HEAD   64
#define D_MLP    4096
#define N_LAYERS 4
#define N_VOCAB  50257
#define N_VOCAB_PAD 50432   // 394*128
#define N_TOKENS 4096       // B*S
#define QKV_N    3072

// -------------------- scratch --------------------
__device__ float  g_resid[N_TOKENS * D_MODEL];
__device__ __half g_xh   [N_TOKENS * D_MODEL];
__device__ __half g_qkvh [N_TOKENS * QKV_N];
__device__ __half g_zh   [N_TOKENS * D_MODEL];
__device__ __half g_hh   [N_TOKENS * D_MLP];
__device__ __half g_wqkv [N_LAYERS * D_MODEL * QKV_N];
__device__ float  g_bqkv [N_LAYERS * QKV_N];
__device__ __half g_wo   [N_LAYERS * D_MODEL * D_MODEL];
__device__ __half g_win  [N_LAYERS * D_MODEL * D_MLP];
__device__ __half g_wout [N_LAYERS * D_MLP * D_MODEL];
__device__ __half g_wu   [D_MODEL * N_VOCAB_PAD];

// -------------------- helpers --------------------
__device__ __forceinline__ float gelu_new(float x) {
  float u = 0.7978845608028654f * (x + 0.044715f * x * x * x);
  return 0.5f * x * (1.0f + tanhf(u));
}
__device__ __forceinline__ void ldsm_x4(uint32_t (&r)[4], uint32_t addr) {
  asm volatile("ldmatrix.sync.aligned.m8n8.x4.shared.b16 {%0,%1,%2,%3}, [%4];"
    : "=r"(r[0]), "=r"(r[1]), "=r"(r[2]), "=r"(r[3]) : "r"(addr));
}
__device__ __forceinline__ void ldsm_x4_t(uint32_t (&r)[4], uint32_t addr) {
  asm volatile("ldmatrix.sync.aligned.m8n8.x4.trans.shared.b16 {%0,%1,%2,%3}, [%4];"
    : "=r"(r[0]), "=r"(r[1]), "=r"(r[2]), "=r"(r[3]) : "r"(addr));
}
__device__ __forceinline__ void mma_f16(float (&c)[4], const uint32_t (&a)[4],
                                        const uint32_t b0, const uint32_t b1) {
  asm volatile("mma.sync.aligned.m16n8k16.row.col.f32.f16.f16.f32 "
    "{%0,%1,%2,%3}, {%4,%5,%6,%7}, {%8,%9}, {%0,%1,%2,%3};"
    : "+f"(c[0]), "+f"(c[1]), "+f"(c[2]), "+f"(c[3])
    : "r"(a[0]), "r"(a[1]), "r"(a[2]), "r"(a[3]), "r"(b0), "r"(b1));
}
__device__ __forceinline__ void cp_async16(uint32_t dst, const void* src) {
  asm volatile("cp.async.cg.shared.global [%0], [%1], 16;\n" :: "r"(dst), "l"(src));
}
__device__ __forceinline__ uint4 pack8(const float4 a, const float4 b) {
  __half2 h0 = __floats2half2_rn(a.x, a.y);
  __half2 h1 = __floats2half2_rn(a.z, a.w);
  __half2 h2 = __floats2half2_rn(b.x, b.y);
  __half2 h3 = __floats2half2_rn(b.z, b.w);
  uint4 r;
  r.x = *reinterpret_cast<uint32_t*>(&h0);
  r.y = *reinterpret_cast<uint32_t*>(&h1);
  r.z = *reinterpret_cast<uint32_t*>(&h2);
  r.w = *reinterpret_cast<uint32_t*>(&h3);
  return r;
}

// -------------------- weight conversion (vectorized) --------------------
// flat fp32 -> fp16, 8 elements per thread (N even cases where out==in layout)
__global__ __launch_bounds__(256) void conv_flat8(
    const float* __restrict__ in, __half* __restrict__ out) {
  size_t i8 = ((size_t)blockIdx.x * 256 + threadIdx.x) * 8;
  float4 a = *reinterpret_cast<const float4*>(in + i8);
  float4 b = *reinterpret_cast<const float4*>(in + i8 + 4);
  *reinterpret_cast<uint4*>(out + i8) = pack8(a, b);
}
// QKV interleave: out[l][k][n], n = which*1024 + h*64 + dh
__global__ __launch_bounds__(256) void conv_qkv8(
    const float* __restrict__ WQ, const float* __restrict__ WK,
    const float* __restrict__ WV, __half* __restrict__ out) {
  size_t i8 = ((size_t)blockIdx.x * 256 + threadIdx.x) * 8;  // over L*1024*3072
  int n = (int)(i8 % QKV_N);
  size_t lk = i8 / QKV_N;
  int k = (int)(lk % D_MODEL);
  int l = (int)(lk / D_MODEL);
  int which = n >> 10, nn = n & 1023;
  int h = nn >> 6, dh = nn & 63;            // dh multiple of 8
  const float* W = (which == 0) ? WQ : ((which == 1) ? WK : WV);
  const float* src = W + (((size_t)l * N_HEADS + h) * D_MODEL + k) * D_HEAD + dh;
  float4 a = *reinterpret_cast<const float4*>(src);
  float4 b = *reinterpret_cast<const float4*>(src + 4);
  *reinterpret_cast<uint4*>(out + i8) = pack8(a, b);
}
// vocab: in [1024][50257] fp32 (odd rows -> scalar loads), out [1024][50432] fp16
__global__ __launch_bounds__(256) void conv_vocab8(
    const float* __restrict__ in, __half* __restrict__ out) {
  int k = blockIdx.y;
  int n = blockIdx.x * 2048 + threadIdx.x * 8;
  if (n >= N_VOCAB_PAD) return;
  const float* row = in + (size_t)k * N_VOCAB;
  float f[8];
#pragma unroll
  for (int u = 0; u < 8; u++) {
    int c = n + u;
    f[u] = (c < N_VOCAB) ? __ldg(row + c) : 0.f;
  }
  float4 a = make_float4(f[0], f[1], f[2], f[3]);
  float4 b = make_float4(f[4], f[5], f[6], f[7]);
  *reinterpret_cast<uint4*>(out + (size_t)k * N_VOCAB_PAD + n) = pack8(a, b);
}
__global__ __launch_bounds__(256) void pack_bias_qkv(
    const float* __restrict__ bq, const float* __restrict__ bk,
    const float* __restrict__ bv, float* __restrict__ out) {
  int i = blockIdx.x * 256 + threadIdx.x;   // L*3072
  int n = i % QKV_N, l = i / QKV_N;
  const float* s = (n < 1024) ? bq : ((n < 2048) ? bk : bv);
  out[i] = s[l * 1024 + (n & 1023)];
}

// -------------------- embedding --------------------
__global__ __launch_bounds__(256) void embed_kernel(
    const int* __restrict__ tok, const float* __restrict__ WE,
    const float* __restrict__ Wp, float* __restrict__ out) {
  int row = blockIdx.x;
  int s = row & (S_LEN - 1);
  int t = threadIdx.x;
  int token = tok[row];
  float4 e = reinterpret_cast<const float4*>(WE + (size_t)token * D_MODEL)[t];
  float4 p = reinterpret_cast<const float4*>(Wp + (size_t)s * D_MODEL)[t];
  float4 r;
  r.x = e.x + p.x; r.y = e.y + p.y; r.z = e.z + p.z; r.w = e.w + p.w;
  reinterpret_cast<float4*>(out + (size_t)row * D_MODEL)[t] = r;
}

// -------------------- layernorm --------------------
__global__ __launch_bounds__(256) void ln_kernel(
    const float* __restrict__ in, const float* __restrict__ w,
    const float* __restrict__ b, __half* __restrict__ out) {
  int row = blockIdx.x;
  int t = threadIdx.x;
  float4 v = reinterpret_cast<const float4*>(in + (size_t)row * D_MODEL)[t];
  float s  = v.x + v.y + v.z + v.w;
  float ss = v.x*v.x + v.y*v.y + v.z*v.z + v.w*v.w;
#pragma unroll
  for (int off = 16; off; off >>= 1) {
    s  += __shfl_xor_sync(0xffffffffu, s,  off);
    ss += __shfl_xor_sync(0xffffffffu, ss, off);
  }
  __shared__ float shs[8], shss[8];
  int wid = t >> 5;
  if ((t & 31) == 0) { shs[wid] = s; shss[wid] = ss; }
  __syncthreads();
  float tot = 0.f, tots = 0.f;
#pragma unroll
  for (int i = 0; i < 8; i++) { tot += shs[i]; tots += shss[i]; }
  float mean = tot * (1.0f / D_MODEL);
  float var  = tots * (1.0f / D_MODEL) - mean * mean;
  float rstd = rsqrtf(var + 1e-5f);
  float4 wv = reinterpret_cast<const float4*>(w)[t];
  float4 bv = reinterpret_cast<const float4*>(b)[t];
  float ox = (v.x - mean) * rstd * wv.x + bv.x;
  float oy = (v.y - mean) * rstd * wv.y + bv.y;
  float oz = (v.z - mean) * rstd * wv.z + bv.z;
  float ow = (v.w - mean) * rstd * wv.w + bv.w;
  __half2* o2 = reinterpret_cast<__half2*>(out + (size_t)row * D_MODEL);
  o2[2 * t]     = __floats2half2_rn(ox, oy);
  o2[2 * t + 1] = __floats2half2_rn(oz, ow);
}

// -------------------- FP16 tensor-core GEMM (256x128, warp 64x64) --------
#define KT        64
#define LDA_B     144
#define LDB_B     272
#define A_BYTES   (256 * LDA_B)   // 36864
#define B_BYTES   (KT * LDB_B)    // 17408
#define STAGE_B   (A_BYTES + B_BYTES)
#define NSTAGES   3
#define GEMM_SMEM (NSTAGES * STAGE_B)

template<bool GELU, bool ACCUM, bool OUTH>
__global__ __launch_bounds__(256, 1) void hgemm(
    const __half* __restrict__ A, const __half* __restrict__ B,
    const float* __restrict__ bias, void* __restrict__ Cv,
    int M, int K, int NB, int Nstore) {
  extern __shared__ __align__(16) char smem[];
  const uint32_t sm = (uint32_t)__cvta_generic_to_shared(smem);

  const int tid  = threadIdx.x;
  const int lane = tid & 31, warp = tid >> 5;
  const int wm = (warp >> 1) * 64;   // 4 warps in M
  const int wn = (warp & 1) * 64;    // 2 warps in N
  const int g = lane >> 2, t = lane & 3;
  const int brow = blockIdx.y * 256, bcol = blockIdx.x * 128;
  const uint32_t laneRow = lane & 15, laneHi = lane >> 4;

  float acc[32][4];
#pragma unroll
  for (int i = 0; i < 32; i++)
#pragma unroll
    for (int j = 0; j < 4; j++) acc[i][j] = 0.f;

  const int NT = K / KT;

  auto stage = [&](int tt) {
    const int k0 = tt * KT;
    const uint32_t sA = sm + (uint32_t)(tt % NSTAGES) * STAGE_B;
    const uint32_t sB = sA + A_BYTES;
    // A: 256 rows x 64 halves (8 chunks of 16B each) -> 2048 chunks
    {
      int slot = tid;
#pragma unroll
      for (int i = 0; i < 8; i++) {
        int r = slot >> 3, ch = slot & 7;
        cp_async16(sA + (uint32_t)r * LDA_B + ch * 16,
                   A + (size_t)(brow + r) * K + k0 + ch * 8);
        slot += 256;
      }
    }
    // B: 64 rows x 128 halves (16 chunks) -> 1024 chunks
    {
      int slot = tid;
#pragma unroll
      for (int i = 0; i < 4; i++) {
        int r = slot >> 4, ch = slot & 15;
        cp_async16(sB + (uint32_t)r * LDB_B + ch * 16,
                   B + (size_t)(k0 + r) * NB + bcol + ch * 8);
        slot += 256;
      }
    }
    asm volatile("cp.async.commit_group;\n" ::: "memory");
  };

  stage(0);
  if (NT > 1) stage(1);

  for (int tt = 0; tt < NT; tt++) {
    if (tt + 1 < NT) {
      asm volatile("cp.async.wait_group 1;\n" ::: "memory");
    } else {
      asm volatile("cp.async.wait_group 0;\n" ::: "memory");
    }
    __syncthreads();
    if (tt + 2 < NT) stage(tt + 2);

    const uint32_t sA = sm + (uint32_t)(tt % NSTAGES) * STAGE_B;
    const uint32_t sB = sA + A_BYTES;

#pragma unroll
    for (int ik = 0; ik < 4; ik++) {
      uint32_t a[4][4];
#pragma unroll
      for (int im = 0; im < 4; im++)
        ldsm_x4(a[im], sA + (uint32_t)(wm + im * 16 + laneRow) * LDA_B
                          + ik * 32 + laneHi * 16);
      uint32_t b[8][2];
#pragma unroll
      for (int jp = 0; jp < 4; jp++) {
        uint32_t r[4];
        ldsm_x4_t(r, sB + (uint32_t)(ik * 16 + laneRow) * LDB_B
                        + (uint32_t)(wn + jp * 16 + laneHi * 8) * 2);
        b[2 * jp][0] = r[0]; b[2 * jp][1] = r[1];
        b[2 * jp + 1][0] = r[2]; b[2 * jp + 1][1] = r[3];
      }
#pragma unroll
      for (int im = 0; im < 4; im++)
#pragma unroll
        for (int jn = 0; jn < 8; jn++)
          mma_f16(acc[im * 8 + jn], a[im], b[jn][0], b[jn][1]);
    }
    __syncthreads();
  }

  float*  Cf = (float*)Cv;
  __half* Ch = (__half*)Cv;
#pragma unroll
  for (int im = 0; im < 4; im++) {
#pragma unroll
    for (int jn = 0; jn < 8; jn++) {
      const float* c = acc[im * 8 + jn];
      int r0 = brow + wm + im * 16 + g;
      int c0 = bcol + wn + jn * 8 + 2 * t;
#pragma unroll
      for (int u = 0; u < 4; u++) {
        int r = r0 + (u >> 1) * 8;
        int cc = c0 + (u & 1);
        if (cc < Nstore) {
          float val = c[u] + bias[cc];
          if (GELU) val = gelu_new(val);
          size_t idx = (size_t)r * Nstore + cc;
          if (OUTH) {
            Ch[idx] = __float2half(val);
          } else {
            if (ACCUM) val += Cf[idx];
            Cf[idx] = val;
          }
        }
      }
    }
  }
}

// -------------------- tensor-core flash attention --------------------
#define ATT_LD 144   // bytes per smem row (72 halves)
__global__ __launch_bounds__(128) void attn_tc(
    const __half* __restrict__ qkv, __half* __restrict__ z) {
  const int b = blockIdx.z, h = blockIdx.y;
  const int q0 = (gridDim.x - 1 - blockIdx.x) * 64;
  const int tid = threadIdx.x;
  const int warp = tid >> 5, lane = tid & 31;
  const int g = lane >> 2, t = lane & 3;

  __shared__ __align__(16) __half sQ[64 * 72];
  __shared__ __align__(16) __half sK[2][64 * 72];
  __shared__ __align__(16) __half sV[2][64 * 72];
  const uint32_t qb = (uint32_t)__cvta_generic_to_shared(sQ);
  const uint32_t kb0 = (uint32_t)__cvta_generic_to_shared(sK[0]);
  const uint32_t kb1 = (uint32_t)__cvta_generic_to_shared(sK[1]);
  const uint32_t vb0 = (uint32_t)__cvta_generic_to_shared(sV[0]);
  const uint32_t vb1 = (uint32_t)__cvta_generic_to_shared(sV[1]);

  for (int slot = tid; slot < 512; slot += 128) {
    int r = slot >> 3, c = slot & 7;
    *reinterpret_cast<uint4*>(&sQ[r * 72 + c * 8]) =
      *reinterpret_cast<const uint4*>(
        qkv + (size_t)(b * S_LEN + q0 + r) * QKV_N + h * D_HEAD + c * 8);
  }
  __syncthreads();

  uint32_t qf[4][4];
#pragma unroll
  for (int ik = 0; ik < 4; ik++)
    ldsm_x4(qf[ik], qb + (uint32_t)(warp * 16 + (lane & 15)) * ATT_LD
                       + ik * 32 + (lane >> 4) * 16);

  const int row0 = q0 + warp * 16 + g;
  const int row1 = row0 + 8;

  float m0 = -INFINITY, m1 = -INFINITY, l0 = 0.f, l1 = 0.f;
  float oacc[8][4];
#pragma unroll
  for (int i = 0; i < 8; i++)
#pragma unroll
    for (int j = 0; j < 4; j++) oacc[i][j] = 0.f;

  const int ntiles = (q0 >> 6) + 1;

  auto stageKV = [&](int tile) {
    const int kt = tile * 64;
    const uint32_t kd = (tile & 1) ? kb1 : kb0;
    const uint32_t vd = (tile & 1) ? vb1 : vb0;
    for (int slot = tid; slot < 512; slot += 128) {
      int r = slot >> 3, c = slot & 7;
      const __half* src = qkv + (size_t)(b * S_LEN + kt + r) * QKV_N
                              + 1024 + h * D_HEAD + c * 8;
      cp_async16(kd + (uint32_t)r * ATT_LD + c * 16, src);
      cp_async16(vd + (uint32_t)r * ATT_LD + c * 16, src + 1024);
    }
    asm volatile("cp.async.commit_group;\n" ::: "memory");
  };

  stageKV(0);

  for (int tile = 0; tile < ntiles; tile++) {
    asm volatile("cp.async.wait_group 0;\n" ::: "memory");
    __syncthreads();
    if (tile + 1 < ntiles) stageKV(tile + 1);

    const uint32_t kd = (tile & 1) ? kb1 : kb0;
    const uint32_t vd = (tile & 1) ? vb1 : vb0;
    const int kt = tile * 64;

    float sacc[8][4];
#pragma unroll
    for (int j = 0; j < 8; j++) {
#pragma unroll
      for (int u = 0; u < 4; u++) sacc[j][u] = 0.f;
      uint32_t bk0[4], bk1[4];
      uint32_t base = kd + (uint32_t)(j * 8 + (lane & 7)) * ATT_LD + (lane >> 3) * 16;
      ldsm_x4(bk0, base);
      ldsm_x4(bk1, base + 64);
      mma_f16(sacc[j], qf[0], bk0[0], bk0[1]);
      mma_f16(sacc[j], qf[1], bk0[2], bk0[3]);
      mma_f16(sacc[j], qf[2], bk1[0], bk1[1]);
      mma_f16(sacc[j], qf[3], bk1[2], bk1[3]);
    }

    float tmx0 = -1e30f, tmx1 = -1e30f;
#pragma unroll
    for (int j = 0; j < 8; j++) {
      int kbase = kt + j * 8 + 2 * t;
      sacc[j][0] = (kbase     <= row0) ? sacc[j][0] * 0.125f : -1e30f;
      sacc[j][1] = (kbase + 1 <= row0) ? sacc[j][1] * 0.125f : -1e30f;
      sacc[j][2] = (kbase     <= row1) ? sacc[j][2] * 0.125f : -1e30f;
      sacc[j][3] = (kbase + 1 <= row1) ? sacc[j][3] * 0.125f : -1e30f;
      tmx0 = fmaxf(tmx0, fmaxf(sacc[j][0], sacc[j][1]));
      tmx1 = fmaxf(tmx1, fmaxf(sacc[j][2], sacc[j][3]));
    }
#pragma unroll
    for (int off = 1; off <= 2; off <<= 1) {
      tmx0 = fmaxf(tmx0, __shfl_xor_sync(0xffffffffu, tmx0, off));
      tmx1 = fmaxf(tmx1, __shfl_xor_sync(0xffffffffu, tmx1, off));
    }
    float mn0 = fmaxf(m0, tmx0), mn1 = fmaxf(m1, tmx1);
    float corr0 = __expf(m0 - mn0), corr1 = __expf(m1 - mn1);
    m0 = mn0; m1 = mn1;

    uint32_t pf[8][2];
    float sum0 = 0.f, sum1 = 0.f;
#pragma unroll
    for (int j = 0; j < 8; j++) {
      float p0 = __expf(sacc[j][0] - mn0);
      float p1 = __expf(sacc[j][1] - mn0);
      float p2 = __expf(sacc[j][2] - mn1);
      float p3 = __expf(sacc[j][3] - mn1);
      sum0 += p0 + p1; sum1 += p2 + p3;
      __half2 h01 = __floats2half2_rn(p0, p1);
      __half2 h23 = __floats2half2_rn(p2, p3);
      pf[j][0] = *reinterpret_cast<uint32_t*>(&h01);
      pf[j][1] = *reinterpret_cast<uint32_t*>(&h23);
    }
#pragma unroll
    for (int off = 1; off <= 2; off <<= 1) {
      sum0 += __shfl_xor_sync(0xffffffffu, sum0, off);
      sum1 += __shfl_xor_sync(0xffffffffu, sum1, off);
    }
    l0 = l0 * corr0 + sum0;
    l1 = l1 * corr1 + sum1;
#pragma unroll
    for (int np = 0; np < 8; np++) {
      oacc[np][0] *= corr0; oacc[np][1] *= corr0;
      oacc[np][2] *= corr1; oacc[np][3] *= corr1;
    }

#pragma unroll
    for (int kk = 0; kk < 4; kk++) {
      uint32_t a[4] = { pf[2 * kk][0], pf[2 * kk][1],
                        pf[2 * kk + 1][0], pf[2 * kk + 1][1] };
#pragma unroll
      for (int np = 0; np < 4; np++) {
        uint32_t r[4];
        ldsm_x4_t(r, vd + (uint32_t)(kk * 16 + (lane & 15)) * ATT_LD
                        + np * 32 + (lane >> 4) * 16);
        mma_f16(oacc[2 * np], a, r[0], r[1]);
        mma_f16(oacc[2 * np + 1], a, r[2], r[3]);
      }
    }
    __syncthreads();
  }

  const float inv0 = 1.0f / l0, inv1 = 1.0f / l1;
#pragma unroll
  for (int np = 0; np < 8; np++) {
    int col = h * D_HEAD + np * 8 + 2 * t;
    __half2 lo = __floats2half2_rn(oacc[np][0] * inv0, oacc[np][1] * inv0);
    __half2 hi = __floats2half2_rn(oacc[np][2] * inv1, oacc[np][3] * inv1);
    *reinterpret_cast<__half2*>(&z[(size_t)(b * S_LEN + row0) * D_MODEL + col]) = lo;
    *reinterpret_cast<__half2*>(&z[(size_t)(b * S_LEN + row1) * D_MODEL + col]) = hi;
  }
}

// -------------------- driver --------------------
template<bool GELU, bool ACCUM, bool OUTH>
static void launch_hgemm(const __half* A, const __half* B, const float* bias,
                         void* C, int M, int K, int NB, int Nstore) {
  cudaFuncSetAttribute(hgemm<GELU, ACCUM, OUTH>,
                       cudaFuncAttributeMaxDynamicSharedMemorySize, GEMM_SMEM);
  dim3 grid(NB / 128, M / 256);
  hgemm<GELU, ACCUM, OUTH><<<grid, 256, GEMM_SMEM>>>(A, B, bias, C, M, K, NB, Nstore);
}

extern "C" void kernel_launch(void* const* d_in, const int* in_sizes, int n_in,
                              void* d_out, int out_size) {
  const int*   tokens = (const int*)  d_in[0];
  const float* W_E    = (const float*)d_in[1];
  const float* W_pos  = (const float*)d_in[2];
  const float* ln1_w  = (const float*)d_in[3];
  const float* ln1_b  = (const float*)d_in[4];
  const float* W_Q    = (const float*)d_in[5];
  const float* b_Q    = (const float*)d_in[6];
  const float* W_K    = (const float*)d_in[7];
  const float* b_K    = (const float*)d_in[8];
  const float* W_V    = (const float*)d_in[9];
  const float* b_V    = (const float*)d_in[10];
  const float* W_O    = (const float*)d_in[11];
  const float* b_O    = (const float*)d_in[12];
  const float* ln2_w  = (const float*)d_in[13];
  const float* ln2_b  = (const float*)d_in[14];
  const float* W_in   = (const float*)d_in[15];
  const float* b_in   = (const float*)d_in[16];
  const float* W_out  = (const float*)d_in[17];
  const float* b_out  = (const float*)d_in[18];
  const float* lnf_w  = (const float*)d_in[19];
  const float* lnf_b  = (const float*)d_in[20];
  const float* W_U    = (const float*)d_in[21];
  const float* b_U    = (const float*)d_in[22];
  float* out = (float*)d_out;

  float *resid, *bqkv;
  __half *xh, *qkvh, *zh, *hh, *wqkv, *wo, *win, *wout, *wu;
  cudaGetSymbolAddress((void**)&resid, g_resid);
  cudaGetSymbolAddress((void**)&xh,    g_xh);
  cudaGetSymbolAddress((void**)&qkvh,  g_qkvh);
  cudaGetSymbolAddress((void**)&zh,    g_zh);
  cudaGetSymbolAddress((void**)&hh,    g_hh);
  cudaGetSymbolAddress((void**)&wqkv,  g_wqkv);
  cudaGetSymbolAddress((void**)&bqkv,  g_bqkv);
  cudaGetSymbolAddress((void**)&wo,    g_wo);
  cudaGetSymbolAddress((void**)&win,   g_win);
  cudaGetSymbolAddress((void**)&wout,  g_wout);
  cudaGetSymbolAddress((void**)&wu,    g_wu);

  conv_qkv8<<<(N_LAYERS * D_MODEL * QKV_N) / 2048, 256>>>(W_Q, W_K, W_V, wqkv);
  pack_bias_qkv<<<(N_LAYERS * QKV_N) / 256, 256>>>(b_Q, b_K, b_V, bqkv);
  // W_O / W_in / W_out are flat fp32->fp16 copies (layout unchanged)
  conv_flat8<<<(N_LAYERS * D_MODEL * D_MODEL) / 2048, 256>>>(W_O, wo);
  conv_flat8<<<(N_LAYERS * D_MODEL * D_MLP) / 2048, 256>>>(W_in, win);
  conv_flat8<<<(N_LAYERS * D_MLP * D_MODEL) / 2048, 256>>>(W_out, wout);
  {
    dim3 gv((N_VOCAB_PAD + 2047) / 2048, D_MODEL);
    conv_vocab8<<<gv, 256>>>(W_U, wu);
  }

  embed_kernel<<<N_TOKENS, 256>>>(tokens, W_E, W_pos, resid);

  dim3 gA(S_LEN / 64, N_HEADS, 2);

  for (int l = 0; l < N_LAYERS; l++) {
    size_t w1 = (size_t)l * D_MODEL * D_MODEL;
    size_t w2 = (size_t)l * D_MODEL * D_MLP;
    const float* l1w = ln1_w + (size_t)l * D_MODEL;
    const float* l1b = ln1_b + (size_t)l * D_MODEL;
    const float* l2w = ln2_w + (size_t)l * D_MODEL;
    const float* l2b = ln2_b + (size_t)l * D_MODEL;

    ln_kernel<<<N_TOKENS, 256>>>(resid, l1w, l1b, xh);
    launch_hgemm<false, false, true>(xh, wqkv + (size_t)l * D_MODEL * QKV_N,
                                     bqkv + (size_t)l * QKV_N, qkvh,
                                     N_TOKENS, D_MODEL, QKV_N, QKV_N);
    attn_tc<<<gA, 128>>>(qkvh, zh);
    launch_hgemm<false, true, false>(zh, wo + w1, b_O + (size_t)l * D_MODEL, resid,
                                     N_TOKENS, D_MODEL, D_MODEL, D_MODEL);
    ln_kernel<<<N_TOKENS, 256>>>(resid, l2w, l2b, xh);
    launch_hgemm<true, false, true>(xh, win + w2, b_in + (size_t)l * D_MLP, hh,
                                    N_TOKENS, D_MODEL, D_MLP, D_MLP);
    launch_hgemm<false, true, false>(hh, wout + w2, b_out + (size_t)l * D_MODEL, resid,
                                     N_TOKENS, D_MLP, D_MODEL, D_MODEL);
  }

  ln_kernel<<<N_TOKENS, 256>>>(resid, lnf_w, lnf_b, xh);
  launch_hgemm<false, false, false>(xh, wu, b_U, out,
                                    N_TOKENS, D_MODEL, N_VOCAB_PAD, N_VOCAB);
}

// round 9
// speedup vs baseline: 1.1501x; 1.1501x over previous
#include <cuda_runtime.h>
#include <cuda_fp16.h>
#include <cstdint>
#include <math.h>

#define S_LEN    2048
#define D_MODEL  1024
#define N_HEADS  16
#define D_HEAD   64
#define D_MLP    4096
#define N_LAYERS 4
#define N_VOCAB  50257
#define N_VOCAB_PAD 50432   // 394*128
#define N_TOKENS 4096       // B*S
#define QKV_N    3072

// -------------------- scratch --------------------
__device__ float  g_resid[N_TOKENS * D_MODEL];
__device__ __half g_xh   [N_TOKENS * D_MODEL];
__device__ __half g_qkvh [N_TOKENS * QKV_N];
__device__ __half g_zh   [N_TOKENS * D_MODEL];
__device__ __half g_hh   [N_TOKENS * D_MLP];
__device__ __half g_wqkv [N_LAYERS * D_MODEL * QKV_N];
__device__ float  g_bqkv [N_LAYERS * QKV_N];
__device__ __half g_wo   [N_LAYERS * D_MODEL * D_MODEL];
__device__ __half g_win  [N_LAYERS * D_MODEL * D_MLP];
__device__ __half g_wout [N_LAYERS * D_MLP * D_MODEL];
__device__ __half g_wu   [D_MODEL * N_VOCAB_PAD];

// -------------------- helpers --------------------
__device__ __forceinline__ float gelu_new(float x) {
  float u = 0.7978845608028654f * (x + 0.044715f * x * x * x);
  return 0.5f * x * (1.0f + tanhf(u));
}
__device__ __forceinline__ void ldsm_x4(uint32_t (&r)[4], uint32_t addr) {
  asm volatile("ldmatrix.sync.aligned.m8n8.x4.shared.b16 {%0,%1,%2,%3}, [%4];"
    : "=r"(r[0]), "=r"(r[1]), "=r"(r[2]), "=r"(r[3]) : "r"(addr));
}
__device__ __forceinline__ void ldsm_x4_t(uint32_t (&r)[4], uint32_t addr) {
  asm volatile("ldmatrix.sync.aligned.m8n8.x4.trans.shared.b16 {%0,%1,%2,%3}, [%4];"
    : "=r"(r[0]), "=r"(r[1]), "=r"(r[2]), "=r"(r[3]) : "r"(addr));
}
__device__ __forceinline__ void mma_f16(float (&c)[4], const uint32_t (&a)[4],
                                        const uint32_t b0, const uint32_t b1) {
  asm volatile("mma.sync.aligned.m16n8k16.row.col.f32.f16.f16.f32 "
    "{%0,%1,%2,%3}, {%4,%5,%6,%7}, {%8,%9}, {%0,%1,%2,%3};"
    : "+f"(c[0]), "+f"(c[1]), "+f"(c[2]), "+f"(c[3])
    : "r"(a[0]), "r"(a[1]), "r"(a[2]), "r"(a[3]), "r"(b0), "r"(b1));
}
__device__ __forceinline__ void cp_async16(uint32_t dst, const void* src) {
  asm volatile("cp.async.cg.shared.global [%0], [%1], 16;\n" :: "r"(dst), "l"(src));
}
__device__ __forceinline__ uint4 pack8(const float4 a, const float4 b) {
  __half2 h0 = __floats2half2_rn(a.x, a.y);
  __half2 h1 = __floats2half2_rn(a.z, a.w);
  __half2 h2 = __floats2half2_rn(b.x, b.y);
  __half2 h3 = __floats2half2_rn(b.z, b.w);
  uint4 r;
  r.x = *reinterpret_cast<uint32_t*>(&h0);
  r.y = *reinterpret_cast<uint32_t*>(&h1);
  r.z = *reinterpret_cast<uint32_t*>(&h2);
  r.w = *reinterpret_cast<uint32_t*>(&h3);
  return r;
}

// -------------------- weight conversion (vectorized) --------------------
__global__ __launch_bounds__(256) void conv_flat8(
    const float* __restrict__ in, __half* __restrict__ out) {
  size_t i8 = ((size_t)blockIdx.x * 256 + threadIdx.x) * 8;
  float4 a = *reinterpret_cast<const float4*>(in + i8);
  float4 b = *reinterpret_cast<const float4*>(in + i8 + 4);
  *reinterpret_cast<uint4*>(out + i8) = pack8(a, b);
}
__global__ __launch_bounds__(256) void conv_qkv8(
    const float* __restrict__ WQ, const float* __restrict__ WK,
    const float* __restrict__ WV, __half* __restrict__ out) {
  size_t i8 = ((size_t)blockIdx.x * 256 + threadIdx.x) * 8;  // over L*1024*3072
  int n = (int)(i8 % QKV_N);
  size_t lk = i8 / QKV_N;
  int k = (int)(lk % D_MODEL);
  int l = (int)(lk / D_MODEL);
  int which = n >> 10, nn = n & 1023;
  int h = nn >> 6, dh = nn & 63;            // dh multiple of 8
  const float* W = (which == 0) ? WQ : ((which == 1) ? WK : WV);
  const float* src = W + (((size_t)l * N_HEADS + h) * D_MODEL + k) * D_HEAD + dh;
  float4 a = *reinterpret_cast<const float4*>(src);
  float4 b = *reinterpret_cast<const float4*>(src + 4);
  *reinterpret_cast<uint4*>(out + i8) = pack8(a, b);
}
__global__ __launch_bounds__(256) void conv_vocab8(
    const float* __restrict__ in, __half* __restrict__ out) {
  int k = blockIdx.y;
  int n = blockIdx.x * 2048 + threadIdx.x * 8;
  if (n >= N_VOCAB_PAD) return;
  const float* row = in + (size_t)k * N_VOCAB;
  float f[8];
#pragma unroll
  for (int u = 0; u < 8; u++) {
    int c = n + u;
    f[u] = (c < N_VOCAB) ? __ldg(row + c) : 0.f;
  }
  float4 a = make_float4(f[0], f[1], f[2], f[3]);
  float4 b = make_float4(f[4], f[5], f[6], f[7]);
  *reinterpret_cast<uint4*>(out + (size_t)k * N_VOCAB_PAD + n) = pack8(a, b);
}
__global__ __launch_bounds__(256) void pack_bias_qkv(
    const float* __restrict__ bq, const float* __restrict__ bk,
    const float* __restrict__ bv, float* __restrict__ out) {
  int i = blockIdx.x * 256 + threadIdx.x;   // L*3072
  int n = i % QKV_N, l = i / QKV_N;
  const float* s = (n < 1024) ? bq : ((n < 2048) ? bk : bv);
  out[i] = s[l * 1024 + (n & 1023)];
}

// -------------------- embedding --------------------
__global__ __launch_bounds__(256) void embed_kernel(
    const int* __restrict__ tok, const float* __restrict__ WE,
    const float* __restrict__ Wp, float* __restrict__ out) {
  int row = blockIdx.x;
  int s = row & (S_LEN - 1);
  int t = threadIdx.x;
  int token = tok[row];
  float4 e = reinterpret_cast<const float4*>(WE + (size_t)token * D_MODEL)[t];
  float4 p = reinterpret_cast<const float4*>(Wp + (size_t)s * D_MODEL)[t];
  float4 r;
  r.x = e.x + p.x; r.y = e.y + p.y; r.z = e.z + p.z; r.w = e.w + p.w;
  reinterpret_cast<float4*>(out + (size_t)row * D_MODEL)[t] = r;
}

// -------------------- layernorm --------------------
__global__ __launch_bounds__(256) void ln_kernel(
    const float* __restrict__ in, const float* __restrict__ w,
    const float* __restrict__ b, __half* __restrict__ out) {
  int row = blockIdx.x;
  int t = threadIdx.x;
  float4 v = reinterpret_cast<const float4*>(in + (size_t)row * D_MODEL)[t];
  float s  = v.x + v.y + v.z + v.w;
  float ss = v.x*v.x + v.y*v.y + v.z*v.z + v.w*v.w;
#pragma unroll
  for (int off = 16; off; off >>= 1) {
    s  += __shfl_xor_sync(0xffffffffu, s,  off);
    ss += __shfl_xor_sync(0xffffffffu, ss, off);
  }
  __shared__ float shs[8], shss[8];
  int wid = t >> 5;
  if ((t & 31) == 0) { shs[wid] = s; shss[wid] = ss; }
  __syncthreads();
  float tot = 0.f, tots = 0.f;
#pragma unroll
  for (int i = 0; i < 8; i++) { tot += shs[i]; tots += shss[i]; }
  float mean = tot * (1.0f / D_MODEL);
  float var  = tots * (1.0f / D_MODEL) - mean * mean;
  float rstd = rsqrtf(var + 1e-5f);
  float4 wv = reinterpret_cast<const float4*>(w)[t];
  float4 bv = reinterpret_cast<const float4*>(b)[t];
  float ox = (v.x - mean) * rstd * wv.x + bv.x;
  float oy = (v.y - mean) * rstd * wv.y + bv.y;
  float oz = (v.z - mean) * rstd * wv.z + bv.z;
  float ow = (v.w - mean) * rstd * wv.w + bv.w;
  __half2* o2 = reinterpret_cast<__half2*>(out + (size_t)row * D_MODEL);
  o2[2 * t]     = __floats2half2_rn(ox, oy);
  o2[2 * t + 1] = __floats2half2_rn(oz, ow);
}

// -------------------- FP16 tensor-core GEMM (128x128, warp 64x32) --------
#define KT        64
#define LDA_B     144
#define LDB_B     272
#define A_BYTES   (128 * LDA_B)
#define B_BYTES   (KT * LDB_B)
#define STAGE_B   (A_BYTES + B_BYTES)
#define NSTAGES   3
#define GEMM_SMEM (NSTAGES * STAGE_B)

template<bool GELU, bool ACCUM, bool OUTH>
__global__ __launch_bounds__(256) void hgemm(
    const __half* __restrict__ A, const __half* __restrict__ B,
    const float* __restrict__ bias, void* __restrict__ Cv,
    int M, int K, int NB, int Nstore) {
  extern __shared__ __align__(16) char smem[];
  const uint32_t sm = (uint32_t)__cvta_generic_to_shared(smem);

  const int tid  = threadIdx.x;
  const int lane = tid & 31, warp = tid >> 5;
  const int wm = (warp >> 2) * 64;
  const int wn = (warp & 3) * 32;
  const int g = lane >> 2, t = lane & 3;
  const int brow = blockIdx.y * 128, bcol = blockIdx.x * 128;
  const uint32_t laneRow = lane & 15, laneHi = lane >> 4;

  float acc[16][4];
#pragma unroll
  for (int i = 0; i < 16; i++)
#pragma unroll
    for (int j = 0; j < 4; j++) acc[i][j] = 0.f;

  const int NT = K / KT;

  auto stage = [&](int tt) {
    const int k0 = tt * KT;
    const uint32_t sA = sm + (uint32_t)(tt % NSTAGES) * STAGE_B;
    const uint32_t sB = sA + A_BYTES;
    {
      int slot = tid;
#pragma unroll
      for (int i = 0; i < 4; i++) {
        int r = slot >> 3, ch = slot & 7;
        cp_async16(sA + (uint32_t)r * LDA_B + ch * 16,
                   A + (size_t)(brow + r) * K + k0 + ch * 8);
        slot += 256;
      }
    }
    {
      int slot = tid;
#pragma unroll
      for (int i = 0; i < 4; i++) {
        int r = slot >> 4, ch = slot & 15;
        cp_async16(sB + (uint32_t)r * LDB_B + ch * 16,
                   B + (size_t)(k0 + r) * NB + bcol + ch * 8);
        slot += 256;
      }
    }
    asm volatile("cp.async.commit_group;\n" ::: "memory");
  };

  stage(0);
  if (NT > 1) stage(1);

  for (int tt = 0; tt < NT; tt++) {
    if (tt + 1 < NT) {
      asm volatile("cp.async.wait_group 1;\n" ::: "memory");
    } else {
      asm volatile("cp.async.wait_group 0;\n" ::: "memory");
    }
    __syncthreads();
    if (tt + 2 < NT) stage(tt + 2);

    const uint32_t sA = sm + (uint32_t)(tt % NSTAGES) * STAGE_B;
    const uint32_t sB = sA + A_BYTES;

#pragma unroll
    for (int ik = 0; ik < 4; ik++) {
      uint32_t a[4][4];
#pragma unroll
      for (int im = 0; im < 4; im++)
        ldsm_x4(a[im], sA + (uint32_t)(wm + im * 16 + laneRow) * LDA_B
                          + ik * 32 + laneHi * 16);
      uint32_t b[4][2];
#pragma unroll
      for (int jp = 0; jp < 2; jp++) {
        uint32_t r[4];
        ldsm_x4_t(r, sB + (uint32_t)(ik * 16 + laneRow) * LDB_B
                        + (uint32_t)(wn + jp * 16 + laneHi * 8) * 2);
        b[2 * jp][0] = r[0]; b[2 * jp][1] = r[1];
        b[2 * jp + 1][0] = r[2]; b[2 * jp + 1][1] = r[3];
      }
#pragma unroll
      for (int im = 0; im < 4; im++)
#pragma unroll
        for (int jn = 0; jn < 4; jn++)
          mma_f16(acc[im * 4 + jn], a[im], b[jn][0], b[jn][1]);
    }
    __syncthreads();
  }

  float*  Cf = (float*)Cv;
  __half* Ch = (__half*)Cv;
#pragma unroll
  for (int im = 0; im < 4; im++) {
#pragma unroll
    for (int jn = 0; jn < 4; jn++) {
      const float* c = acc[im * 4 + jn];
      int r0 = brow + wm + im * 16 + g;
      int c0 = bcol + wn + jn * 8 + 2 * t;
#pragma unroll
      for (int u = 0; u < 4; u++) {
        int r = r0 + (u >> 1) * 8;
        int cc = c0 + (u & 1);
        if (cc < Nstore) {
          float val = c[u] + bias[cc];
          if (GELU) val = gelu_new(val);
          size_t idx = (size_t)r * Nstore + cc;
          if (OUTH) {
            Ch[idx] = __float2half(val);
          } else {
            if (ACCUM) val += Cf[idx];
            Cf[idx] = val;
          }
        }
      }
    }
  }
}

// -------------------- tensor-core flash attention --------------------
#define ATT_LD 144   // bytes per smem row (72 halves)
__global__ __launch_bounds__(128) void attn_tc(
    const __half* __restrict__ qkv, __half* __restrict__ z) {
  const int b = blockIdx.z, h = blockIdx.y;
  const int q0 = (gridDim.x - 1 - blockIdx.x) * 64;
  const int tid = threadIdx.x;
  const int warp = tid >> 5, lane = tid & 31;
  const int g = lane >> 2, t = lane & 3;

  __shared__ __align__(16) __half sQ[64 * 72];
  __shared__ __align__(16) __half sK[2][64 * 72];
  __shared__ __align__(16) __half sV[2][64 * 72];
  const uint32_t qb = (uint32_t)__cvta_generic_to_shared(sQ);
  const uint32_t kb0 = (uint32_t)__cvta_generic_to_shared(sK[0]);
  const uint32_t kb1 = (uint32_t)__cvta_generic_to_shared(sK[1]);
  const uint32_t vb0 = (uint32_t)__cvta_generic_to_shared(sV[0]);
  const uint32_t vb1 = (uint32_t)__cvta_generic_to_shared(sV[1]);

  for (int slot = tid; slot < 512; slot += 128) {
    int r = slot >> 3, c = slot & 7;
    *reinterpret_cast<uint4*>(&sQ[r * 72 + c * 8]) =
      *reinterpret_cast<const uint4*>(
        qkv + (size_t)(b * S_LEN + q0 + r) * QKV_N + h * D_HEAD + c * 8);
  }
  __syncthreads();

  uint32_t qf[4][4];
#pragma unroll
  for (int ik = 0; ik < 4; ik++)
    ldsm_x4(qf[ik], qb + (uint32_t)(warp * 16 + (lane & 15)) * ATT_LD
                       + ik * 32 + (lane >> 4) * 16);

  const int row0 = q0 + warp * 16 + g;
  const int row1 = row0 + 8;

  float m0 = -INFINITY, m1 = -INFINITY, l0 = 0.f, l1 = 0.f;
  float oacc[8][4];
#pragma unroll
  for (int i = 0; i < 8; i++)
#pragma unroll
    for (int j = 0; j < 4; j++) oacc[i][j] = 0.f;

  const int ntiles = (q0 >> 6) + 1;

  auto stageKV = [&](int tile) {
    const int kt = tile * 64;
    const uint32_t kd = (tile & 1) ? kb1 : kb0;
    const uint32_t vd = (tile & 1) ? vb1 : vb0;
    for (int slot = tid; slot < 512; slot += 128) {
      int r = slot >> 3, c = slot & 7;
      const __half* src = qkv + (size_t)(b * S_LEN + kt + r) * QKV_N
                              + 1024 + h * D_HEAD + c * 8;
      cp_async16(kd + (uint32_t)r * ATT_LD + c * 16, src);
      cp_async16(vd + (uint32_t)r * ATT_LD + c * 16, src + 1024);
    }
    asm volatile("cp.async.commit_group;\n" ::: "memory");
  };

  stageKV(0);

  for (int tile = 0; tile < ntiles; tile++) {
    asm volatile("cp.async.wait_group 0;\n" ::: "memory");
    __syncthreads();
    if (tile + 1 < ntiles) stageKV(tile + 1);

    const uint32_t kd = (tile & 1) ? kb1 : kb0;
    const uint32_t vd = (tile & 1) ? vb1 : vb0;
    const int kt = tile * 64;

    float sacc[8][4];
#pragma unroll
    for (int j = 0; j < 8; j++) {
#pragma unroll
      for (int u = 0; u < 4; u++) sacc[j][u] = 0.f;
      uint32_t bk0[4], bk1[4];
      uint32_t base = kd + (uint32_t)(j * 8 + (lane & 7)) * ATT_LD + (lane >> 3) * 16;
      ldsm_x4(bk0, base);
      ldsm_x4(bk1, base + 64);
      mma_f16(sacc[j], qf[0], bk0[0], bk0[1]);
      mma_f16(sacc[j], qf[1], bk0[2], bk0[3]);
      mma_f16(sacc[j], qf[2], bk1[0], bk1[1]);
      mma_f16(sacc[j], qf[3], bk1[2], bk1[3]);
    }

    float tmx0 = -1e30f, tmx1 = -1e30f;
#pragma unroll
    for (int j = 0; j < 8; j++) {
      int kbase = kt + j * 8 + 2 * t;
      sacc[j][0] = (kbase     <= row0) ? sacc[j][0] * 0.125f : -1e30f;
      sacc[j][1] = (kbase + 1 <= row0) ? sacc[j][1] * 0.125f : -1e30f;
      sacc[j][2] = (kbase     <= row1) ? sacc[j][2] * 0.125f : -1e30f;
      sacc[j][3] = (kbase + 1 <= row1) ? sacc[j][3] * 0.125f : -1e30f;
      tmx0 = fmaxf(tmx0, fmaxf(sacc[j][0], sacc[j][1]));
      tmx1 = fmaxf(tmx1, fmaxf(sacc[j][2], sacc[j][3]));
    }
#pragma unroll
    for (int off = 1; off <= 2; off <<= 1) {
      tmx0 = fmaxf(tmx0, __shfl_xor_sync(0xffffffffu, tmx0, off));
      tmx1 = fmaxf(tmx1, __shfl_xor_sync(0xffffffffu, tmx1, off));
    }
    float mn0 = fmaxf(m0, tmx0), mn1 = fmaxf(m1, tmx1);
    float corr0 = __expf(m0 - mn0), corr1 = __expf(m1 - mn1);
    m0 = mn0; m1 = mn1;

    uint32_t pf[8][2];
    float sum0 = 0.f, sum1 = 0.f;
#pragma unroll
    for (int j = 0; j < 8; j++) {
      float p0 = __expf(sacc[j][0] - mn0);
      float p1 = __expf(sacc[j][1] - mn0);
      float p2 = __expf(sacc[j][2] - mn1);
      float p3 = __expf(sacc[j][3] - mn1);
      sum0 += p0 + p1; sum1 += p2 + p3;
      __half2 h01 = __floats2half2_rn(p0, p1);
      __half2 h23 = __floats2half2_rn(p2, p3);
      pf[j][0] = *reinterpret_cast<uint32_t*>(&h01);
      pf[j][1] = *reinterpret_cast<uint32_t*>(&h23);
    }
#pragma unroll
    for (int off = 1; off <= 2; off <<= 1) {
      sum0 += __shfl_xor_sync(0xffffffffu, sum0, off);
      sum1 += __shfl_xor_sync(0xffffffffu, sum1, off);
    }
    l0 = l0 * corr0 + sum0;
    l1 = l1 * corr1 + sum1;
#pragma unroll
    for (int np = 0; np < 8; np++) {
      oacc[np][0] *= corr0; oacc[np][1] *= corr0;
      oacc[np][2] *= corr1; oacc[np][3] *= corr1;
    }

#pragma unroll
    for (int kk = 0; kk < 4; kk++) {
      uint32_t a[4] = { pf[2 * kk][0], pf[2 * kk][1],
                        pf[2 * kk + 1][0], pf[2 * kk + 1][1] };
#pragma unroll
      for (int np = 0; np < 4; np++) {
        uint32_t r[4];
        ldsm_x4_t(r, vd + (uint32_t)(kk * 16 + (lane & 15)) * ATT_LD
                        + np * 32 + (lane >> 4) * 16);
        mma_f16(oacc[2 * np], a, r[0], r[1]);
        mma_f16(oacc[2 * np + 1], a, r[2], r[3]);
      }
    }
    __syncthreads();
  }

  const float inv0 = 1.0f / l0, inv1 = 1.0f / l1;
#pragma unroll
  for (int np = 0; np < 8; np++) {
    int col = h * D_HEAD + np * 8 + 2 * t;
    __half2 lo = __floats2half2_rn(oacc[np][0] * inv0, oacc[np][1] * inv0);
    __half2 hi = __floats2half2_rn(oacc[np][2] * inv1, oacc[np][3] * inv1);
    *reinterpret_cast<__half2*>(&z[(size_t)(b * S_LEN + row0) * D_MODEL + col]) = lo;
    *reinterpret_cast<__half2*>(&z[(size_t)(b * S_LEN + row1) * D_MODEL + col]) = hi;
  }
}

// -------------------- driver --------------------
template<bool GELU, bool ACCUM, bool OUTH>
static void launch_hgemm(const __half* A, const __half* B, const float* bias,
                         void* C, int M, int K, int NB, int Nstore) {
  cudaFuncSetAttribute(hgemm<GELU, ACCUM, OUTH>,
                       cudaFuncAttributeMaxDynamicSharedMemorySize, GEMM_SMEM);
  dim3 grid(NB / 128, M / 128);
  hgemm<GELU, ACCUM, OUTH><<<grid, 256, GEMM_SMEM>>>(A, B, bias, C, M, K, NB, Nstore);
}

extern "C" void kernel_launch(void* const* d_in, const int* in_sizes, int n_in,
                              void* d_out, int out_size) {
  const int*   tokens = (const int*)  d_in[0];
  const float* W_E    = (const float*)d_in[1];
  const float* W_pos  = (const float*)d_in[2];
  const float* ln1_w  = (const float*)d_in[3];
  const float* ln1_b  = (const float*)d_in[4];
  const float* W_Q    = (const float*)d_in[5];
  const float* b_Q    = (const float*)d_in[6];
  const float* W_K    = (const float*)d_in[7];
  const float* b_K    = (const float*)d_in[8];
  const float* W_V    = (const float*)d_in[9];
  const float* b_V    = (const float*)d_in[10];
  const float* W_O    = (const float*)d_in[11];
  const float* b_O    = (const float*)d_in[12];
  const float* ln2_w  = (const float*)d_in[13];
  const float* ln2_b  = (const float*)d_in[14];
  const float* W_in   = (const float*)d_in[15];
  const float* b_in   = (const float*)d_in[16];
  const float* W_out  = (const float*)d_in[17];
  const float* b_out  = (const float*)d_in[18];
  const float* lnf_w  = (const float*)d_in[19];
  const float* lnf_b  = (const float*)d_in[20];
  const float* W_U    = (const float*)d_in[21];
  const float* b_U    = (const float*)d_in[22];
  float* out = (float*)d_out;

  float *resid, *bqkv;
  __half *xh, *qkvh, *zh, *hh, *wqkv, *wo, *win, *wout, *wu;
  cudaGetSymbolAddress((void**)&resid, g_resid);
  cudaGetSymbolAddress((void**)&xh,    g_xh);
  cudaGetSymbolAddress((void**)&qkvh,  g_qkvh);
  cudaGetSymbolAddress((void**)&zh,    g_zh);
  cudaGetSymbolAddress((void**)&hh,    g_hh);
  cudaGetSymbolAddress((void**)&wqkv,  g_wqkv);
  cudaGetSymbolAddress((void**)&bqkv,  g_bqkv);
  cudaGetSymbolAddress((void**)&wo,    g_wo);
  cudaGetSymbolAddress((void**)&win,   g_win);
  cudaGetSymbolAddress((void**)&wout,  g_wout);
  cudaGetSymbolAddress((void**)&wu,    g_wu);

  conv_qkv8<<<(N_LAYERS * D_MODEL * QKV_N) / 2048, 256>>>(W_Q, W_K, W_V, wqkv);
  pack_bias_qkv<<<(N_LAYERS * QKV_N) / 256, 256>>>(b_Q, b_K, b_V, bqkv);
  conv_flat8<<<(N_LAYERS * D_MODEL * D_MODEL) / 2048, 256>>>(W_O, wo);
  conv_flat8<<<(N_LAYERS * D_MODEL * D_MLP) / 2048, 256>>>(W_in, win);
  conv_flat8<<<(N_LAYERS * D_MLP * D_MODEL) / 2048, 256>>>(W_out, wout);
  {
    dim3 gv((N_VOCAB_PAD + 2047) / 2048, D_MODEL);
    conv_vocab8<<<gv, 256>>>(W_U, wu);
  }

  embed_kernel<<<N_TOKENS, 256>>>(tokens, W_E, W_pos, resid);

  dim3 gA(S_LEN / 64, N_HEADS, 2);

  for (int l = 0; l < N_LAYERS; l++) {
    size_t w1 = (size_t)l * D_MODEL * D_MODEL;
    size_t w2 = (size_t)l * D_MODEL * D_MLP;
    const float* l1w = ln1_w + (size_t)l * D_MODEL;
    const float* l1b = ln1_b + (size_t)l * D_MODEL;
    const float* l2w = ln2_w + (size_t)l * D_MODEL;
    const float* l2b = ln2_b + (size_t)l * D_MODEL;

    ln_kernel<<<N_TOKENS, 256>>>(resid, l1w, l1b, xh);
    launch_hgemm<false, false, true>(xh, wqkv + (size_t)l * D_MODEL * QKV_N,
                                     bqkv + (size_t)l * QKV_N, qkvh,
                                     N_TOKENS, D_MODEL, QKV_N, QKV_N);
    attn_tc<<<gA, 128>>>(qkvh, zh);
    launch_hgemm<false, true, false>(zh, wo + w1, b_O + (size_t)l * D_MODEL, resid,
                                     N_TOKENS, D_MODEL, D_MODEL, D_MODEL);
    ln_kernel<<<N_TOKENS, 256>>>(resid, l2w, l2b, xh);
    launch_hgemm<true, false, true>(xh, win + w2, b_in + (size_t)l * D_MLP, hh,
                                    N_TOKENS, D_MODEL, D_MLP, D_MLP);
    launch_hgemm<false, true, false>(hh, wout + w2, b_out + (size_t)l * D_MODEL, resid,
                                     N_TOKENS, D_MLP, D_MODEL, D_MODEL);
  }

  ln_kernel<<<N_TOKENS, 256>>>(resid, lnf_w, lnf_b, xh);
  launch_hgemm<false, false, false>(xh, wu, b_U, out,
                                    N_TOKENS, D_MODEL, N_VOCAB_PAD, N_VOCAB);
}

// round 10
// speedup vs baseline: 1.1507x; 1.0005x over previous
#include <cuda_runtime.h>
#include <cuda_fp16.h>
#include <cstdint>
#include <math.h>

#define S_LEN    2048
#define D_MODEL  1024
#define N_HEADS  16
#define D_HEAD   64
#define D_MLP    4096
#define N_LAYERS 4
#define N_VOCAB  50257
#define N_VOCAB_PAD 50432   // 394*128
#define N_TOKENS 4096       // B*S
#define QKV_N    3072

// -------------------- scratch --------------------
__device__ float  g_resid[N_TOKENS * D_MODEL];
__device__ __half g_xh   [N_TOKENS * D_MODEL];
__device__ __half g_qkvh [N_TOKENS * QKV_N];
__device__ __half g_zh   [N_TOKENS * D_MODEL];
__device__ __half g_hh   [N_TOKENS * D_MLP];
__device__ __half g_wqkv [N_LAYERS * D_MODEL * QKV_N];
__device__ float  g_bqkv [N_LAYERS * QKV_N];
__device__ __half g_wo   [N_LAYERS * D_MODEL * D_MODEL];
__device__ __half g_win  [N_LAYERS * D_MODEL * D_MLP];
__device__ __half g_wout [N_LAYERS * D_MLP * D_MODEL];
__device__ __half g_wu   [D_MODEL * N_VOCAB_PAD];

// -------------------- helpers --------------------
__device__ __forceinline__ float gelu_new(float x) {
  float u = 0.7978845608028654f * (x + 0.044715f * x * x * x);
  return 0.5f * x * (1.0f + tanhf(u));
}
__device__ __forceinline__ void ldsm_x4(uint32_t (&r)[4], uint32_t addr) {
  asm volatile("ldmatrix.sync.aligned.m8n8.x4.shared.b16 {%0,%1,%2,%3}, [%4];"
    : "=r"(r[0]), "=r"(r[1]), "=r"(r[2]), "=r"(r[3]) : "r"(addr));
}
__device__ __forceinline__ void ldsm_x4_t(uint32_t (&r)[4], uint32_t addr) {
  asm volatile("ldmatrix.sync.aligned.m8n8.x4.trans.shared.b16 {%0,%1,%2,%3}, [%4];"
    : "=r"(r[0]), "=r"(r[1]), "=r"(r[2]), "=r"(r[3]) : "r"(addr));
}
__device__ __forceinline__ void mma_f16(float (&c)[4], const uint32_t (&a)[4],
                                        const uint32_t b0, const uint32_t b1) {
  asm volatile("mma.sync.aligned.m16n8k16.row.col.f32.f16.f16.f32 "
    "{%0,%1,%2,%3}, {%4,%5,%6,%7}, {%8,%9}, {%0,%1,%2,%3};"
    : "+f"(c[0]), "+f"(c[1]), "+f"(c[2]), "+f"(c[3])
    : "r"(a[0]), "r"(a[1]), "r"(a[2]), "r"(a[3]), "r"(b0), "r"(b1));
}
__device__ __forceinline__ void cp_async16(uint32_t dst, const void* src) {
  asm volatile("cp.async.cg.shared.global [%0], [%1], 16;\n" :: "r"(dst), "l"(src));
}
__device__ __forceinline__ uint4 pack8(const float4 a, const float4 b) {
  __half2 h0 = __floats2half2_rn(a.x, a.y);
  __half2 h1 = __floats2half2_rn(a.z, a.w);
  __half2 h2 = __floats2half2_rn(b.x, b.y);
  __half2 h3 = __floats2half2_rn(b.z, b.w);
  uint4 r;
  r.x = *reinterpret_cast<uint32_t*>(&h0);
  r.y = *reinterpret_cast<uint32_t*>(&h1);
  r.z = *reinterpret_cast<uint32_t*>(&h2);
  r.w = *reinterpret_cast<uint32_t*>(&h3);
  return r;
}

// -------------------- weight conversion (vectorized) --------------------
__global__ __launch_bounds__(256) void conv_flat8(
    const float* __restrict__ in, __half* __restrict__ out) {
  size_t i8 = ((size_t)blockIdx.x * 256 + threadIdx.x) * 8;
  float4 a = *reinterpret_cast<const float4*>(in + i8);
  float4 b = *reinterpret_cast<const float4*>(in + i8 + 4);
  *reinterpret_cast<uint4*>(out + i8) = pack8(a, b);
}
__global__ __launch_bounds__(256) void conv_qkv8(
    const float* __restrict__ WQ, const float* __restrict__ WK,
    const float* __restrict__ WV, __half* __restrict__ out) {
  size_t i8 = ((size_t)blockIdx.x * 256 + threadIdx.x) * 8;  // over L*1024*3072
  int n = (int)(i8 % QKV_N);
  size_t lk = i8 / QKV_N;
  int k = (int)(lk % D_MODEL);
  int l = (int)(lk / D_MODEL);
  int which = n >> 10, nn = n & 1023;
  int h = nn >> 6, dh = nn & 63;            // dh multiple of 8
  const float* W = (which == 0) ? WQ : ((which == 1) ? WK : WV);
  const float* src = W + (((size_t)l * N_HEADS + h) * D_MODEL + k) * D_HEAD + dh;
  float4 a = *reinterpret_cast<const float4*>(src);
  float4 b = *reinterpret_cast<const float4*>(src + 4);
  *reinterpret_cast<uint4*>(out + i8) = pack8(a, b);
}
__global__ __launch_bounds__(256) void conv_vocab8(
    const float* __restrict__ in, __half* __restrict__ out) {
  int k = blockIdx.y;
  int n = blockIdx.x * 2048 + threadIdx.x * 8;
  if (n >= N_VOCAB_PAD) return;
  const float* row = in + (size_t)k * N_VOCAB;
  float f[8];
#pragma unroll
  for (int u = 0; u < 8; u++) {
    int c = n + u;
    f[u] = (c < N_VOCAB) ? __ldg(row + c) : 0.f;
  }
  float4 a = make_float4(f[0], f[1], f[2], f[3]);
  float4 b = make_float4(f[4], f[5], f[6], f[7]);
  *reinterpret_cast<uint4*>(out + (size_t)k * N_VOCAB_PAD + n) = pack8(a, b);
}
__global__ __launch_bounds__(256) void pack_bias_qkv(
    const float* __restrict__ bq, const float* __restrict__ bk,
    const float* __restrict__ bv, float* __restrict__ out) {
  int i = blockIdx.x * 256 + threadIdx.x;   // L*3072
  int n = i % QKV_N, l = i / QKV_N;
  const float* s = (n < 1024) ? bq : ((n < 2048) ? bk : bv);
  out[i] = s[l * 1024 + (n & 1023)];
}

// -------------------- embedding --------------------
__global__ __launch_bounds__(256) void embed_kernel(
    const int* __restrict__ tok, const float* __restrict__ WE,
    const float* __restrict__ Wp, float* __restrict__ out) {
  int row = blockIdx.x;
  int s = row & (S_LEN - 1);
  int t = threadIdx.x;
  int token = tok[row];
  float4 e = reinterpret_cast<const float4*>(WE + (size_t)token * D_MODEL)[t];
  float4 p = reinterpret_cast<const float4*>(Wp + (size_t)s * D_MODEL)[t];
  float4 r;
  r.x = e.x + p.x; r.y = e.y + p.y; r.z = e.z + p.z; r.w = e.w + p.w;
  reinterpret_cast<float4*>(out + (size_t)row * D_MODEL)[t] = r;
}

// -------------------- layernorm --------------------
__global__ __launch_bounds__(256) void ln_kernel(
    const float* __restrict__ in, const float* __restrict__ w,
    const float* __restrict__ b, __half* __restrict__ out) {
  int row = blockIdx.x;
  int t = threadIdx.x;
  float4 v = reinterpret_cast<const float4*>(in + (size_t)row * D_MODEL)[t];
  float s  = v.x + v.y + v.z + v.w;
  float ss = v.x*v.x + v.y*v.y + v.z*v.z + v.w*v.w;
#pragma unroll
  for (int off = 16; off; off >>= 1) {
    s  += __shfl_xor_sync(0xffffffffu, s,  off);
    ss += __shfl_xor_sync(0xffffffffu, ss, off);
  }
  __shared__ float shs[8], shss[8];
  int wid = t >> 5;
  if ((t & 31) == 0) { shs[wid] = s; shss[wid] = ss; }
  __syncthreads();
  float tot = 0.f, tots = 0.f;
#pragma unroll
  for (int i = 0; i < 8; i++) { tot += shs[i]; tots += shss[i]; }
  float mean = tot * (1.0f / D_MODEL);
  float var  = tots * (1.0f / D_MODEL) - mean * mean;
  float rstd = rsqrtf(var + 1e-5f);
  float4 wv = reinterpret_cast<const float4*>(w)[t];
  float4 bv = reinterpret_cast<const float4*>(b)[t];
  float ox = (v.x - mean) * rstd * wv.x + bv.x;
  float oy = (v.y - mean) * rstd * wv.y + bv.y;
  float oz = (v.z - mean) * rstd * wv.z + bv.z;
  float ow = (v.w - mean) * rstd * wv.w + bv.w;
  __half2* o2 = reinterpret_cast<__half2*>(out + (size_t)row * D_MODEL);
  o2[2 * t]     = __floats2half2_rn(ox, oy);
  o2[2 * t + 1] = __floats2half2_rn(oz, ow);
}

// -------------------- FP16 tensor-core GEMM (128x128, warp 64x32) --------
// SWAP: if true, blockIdx.x indexes M (fastest) so consecutive CTAs share the
// same B tile -> B gets L2 reuse (used for the 103MB vocab weight).
#define KT        64
#define LDA_B     144
#define LDB_B     272
#define A_BYTES   (128 * LDA_B)
#define B_BYTES   (KT * LDB_B)
#define STAGE_B   (A_BYTES + B_BYTES)
#define NSTAGES   3
#define GEMM_SMEM (NSTAGES * STAGE_B)

template<bool GELU, bool ACCUM, bool OUTH, bool SWAP>
__global__ __launch_bounds__(256) void hgemm(
    const __half* __restrict__ A, const __half* __restrict__ B,
    const float* __restrict__ bias, void* __restrict__ Cv,
    int M, int K, int NB, int Nstore) {
  extern __shared__ __align__(16) char smem[];
  const uint32_t sm = (uint32_t)__cvta_generic_to_shared(smem);

  const int tid  = threadIdx.x;
  const int lane = tid & 31, warp = tid >> 5;
  const int wm = (warp >> 2) * 64;
  const int wn = (warp & 3) * 32;
  const int g = lane >> 2, t = lane & 3;
  const int brow = (SWAP ? blockIdx.x : blockIdx.y) * 128;
  const int bcol = (SWAP ? blockIdx.y : blockIdx.x) * 128;
  const uint32_t laneRow = lane & 15, laneHi = lane >> 4;

  float acc[16][4];
#pragma unroll
  for (int i = 0; i < 16; i++)
#pragma unroll
    for (int j = 0; j < 4; j++) acc[i][j] = 0.f;

  const int NT = K / KT;

  auto stage = [&](int tt) {
    const int k0 = tt * KT;
    const uint32_t sA = sm + (uint32_t)(tt % NSTAGES) * STAGE_B;
    const uint32_t sB = sA + A_BYTES;
    {
      int slot = tid;
#pragma unroll
      for (int i = 0; i < 4; i++) {
        int r = slot >> 3, ch = slot & 7;
        cp_async16(sA + (uint32_t)r * LDA_B + ch * 16,
                   A + (size_t)(brow + r) * K + k0 + ch * 8);
        slot += 256;
      }
    }
    {
      int slot = tid;
#pragma unroll
      for (int i = 0; i < 4; i++) {
        int r = slot >> 4, ch = slot & 15;
        cp_async16(sB + (uint32_t)r * LDB_B + ch * 16,
                   B + (size_t)(k0 + r) * NB + bcol + ch * 8);
        slot += 256;
      }
    }
    asm volatile("cp.async.commit_group;\n" ::: "memory");
  };

  stage(0);
  if (NT > 1) stage(1);

  for (int tt = 0; tt < NT; tt++) {
    if (tt + 1 < NT) {
      asm volatile("cp.async.wait_group 1;\n" ::: "memory");
    } else {
      asm volatile("cp.async.wait_group 0;\n" ::: "memory");
    }
    __syncthreads();
    if (tt + 2 < NT) stage(tt + 2);

    const uint32_t sA = sm + (uint32_t)(tt % NSTAGES) * STAGE_B;
    const uint32_t sB = sA + A_BYTES;

#pragma unroll
    for (int ik = 0; ik < 4; ik++) {
      uint32_t a[4][4];
#pragma unroll
      for (int im = 0; im < 4; im++)
        ldsm_x4(a[im], sA + (uint32_t)(wm + im * 16 + laneRow) * LDA_B
                          + ik * 32 + laneHi * 16);
      uint32_t b[4][2];
#pragma unroll
      for (int jp = 0; jp < 2; jp++) {
        uint32_t r[4];
        ldsm_x4_t(r, sB + (uint32_t)(ik * 16 + laneRow) * LDB_B
                        + (uint32_t)(wn + jp * 16 + laneHi * 8) * 2);
        b[2 * jp][0] = r[0]; b[2 * jp][1] = r[1];
        b[2 * jp + 1][0] = r[2]; b[2 * jp + 1][1] = r[3];
      }
#pragma unroll
      for (int im = 0; im < 4; im++)
#pragma unroll
        for (int jn = 0; jn < 4; jn++)
          mma_f16(acc[im * 4 + jn], a[im], b[jn][0], b[jn][1]);
    }
    __syncthreads();
  }

  float*  Cf = (float*)Cv;
  __half* Ch = (__half*)Cv;
#pragma unroll
  for (int im = 0; im < 4; im++) {
#pragma unroll
    for (int jn = 0; jn < 4; jn++) {
      const float* c = acc[im * 4 + jn];
      int r0 = brow + wm + im * 16 + g;
      int c0 = bcol + wn + jn * 8 + 2 * t;
#pragma unroll
      for (int u = 0; u < 4; u++) {
        int r = r0 + (u >> 1) * 8;
        int cc = c0 + (u & 1);
        if (cc < Nstore) {
          float val = c[u] + bias[cc];
          if (GELU) val = gelu_new(val);
          size_t idx = (size_t)r * Nstore + cc;
          if (OUTH) {
            Ch[idx] = __float2half(val);
          } else {
            if (ACCUM) val += Cf[idx];
            Cf[idx] = val;
          }
        }
      }
    }
  }
}

// -------------------- tensor-core flash attention --------------------
#define ATT_LD 144   // bytes per smem row (72 halves)
__global__ __launch_bounds__(128) void attn_tc(
    const __half* __restrict__ qkv, __half* __restrict__ z) {
  const int b = blockIdx.z, h = blockIdx.y;
  const int q0 = (gridDim.x - 1 - blockIdx.x) * 64;
  const int tid = threadIdx.x;
  const int warp = tid >> 5, lane = tid & 31;
  const int g = lane >> 2, t = lane & 3;

  __shared__ __align__(16) __half sQ[64 * 72];
  __shared__ __align__(16) __half sK[2][64 * 72];
  __shared__ __align__(16) __half sV[2][64 * 72];
  const uint32_t qb = (uint32_t)__cvta_generic_to_shared(sQ);
  const uint32_t kb0 = (uint32_t)__cvta_generic_to_shared(sK[0]);
  const uint32_t kb1 = (uint32_t)__cvta_generic_to_shared(sK[1]);
  const uint32_t vb0 = (uint32_t)__cvta_generic_to_shared(sV[0]);
  const uint32_t vb1 = (uint32_t)__cvta_generic_to_shared(sV[1]);

  for (int slot = tid; slot < 512; slot += 128) {
    int r = slot >> 3, c = slot & 7;
    *reinterpret_cast<uint4*>(&sQ[r * 72 + c * 8]) =
      *reinterpret_cast<const uint4*>(
        qkv + (size_t)(b * S_LEN + q0 + r) * QKV_N + h * D_HEAD + c * 8);
  }
  __syncthreads();

  uint32_t qf[4][4];
#pragma unroll
  for (int ik = 0; ik < 4; ik++)
    ldsm_x4(qf[ik], qb + (uint32_t)(warp * 16 + (lane & 15)) * ATT_LD
                       + ik * 32 + (lane >> 4) * 16);

  const int row0 = q0 + warp * 16 + g;
  const int row1 = row0 + 8;

  float m0 = -INFINITY, m1 = -INFINITY, l0 = 0.f, l1 = 0.f;
  float oacc[8][4];
#pragma unroll
  for (int i = 0; i < 8; i++)
#pragma unroll
    for (int j = 0; j < 4; j++) oacc[i][j] = 0.f;

  const int ntiles = (q0 >> 6) + 1;

  auto stageKV = [&](int tile) {
    const int kt = tile * 64;
    const uint32_t kd = (tile & 1) ? kb1 : kb0;
    const uint32_t vd = (tile & 1) ? vb1 : vb0;
    for (int slot = tid; slot < 512; slot += 128) {
      int r = slot >> 3, c = slot & 7;
      const __half* src = qkv + (size_t)(b * S_LEN + kt + r) * QKV_N
                              + 1024 + h * D_HEAD + c * 8;
      cp_async16(kd + (uint32_t)r * ATT_LD + c * 16, src);
      cp_async16(vd + (uint32_t)r * ATT_LD + c * 16, src + 1024);
    }
    asm volatile("cp.async.commit_group;\n" ::: "memory");
  };

  stageKV(0);

  for (int tile = 0; tile < ntiles; tile++) {
    asm volatile("cp.async.wait_group 0;\n" ::: "memory");
    __syncthreads();
    if (tile + 1 < ntiles) stageKV(tile + 1);

    const uint32_t kd = (tile & 1) ? kb1 : kb0;
    const uint32_t vd = (tile & 1) ? vb1 : vb0;
    const int kt = tile * 64;

    float sacc[8][4];
#pragma unroll
    for (int j = 0; j < 8; j++) {
#pragma unroll
      for (int u = 0; u < 4; u++) sacc[j][u] = 0.f;
      uint32_t bk0[4], bk1[4];
      uint32_t base = kd + (uint32_t)(j * 8 + (lane & 7)) * ATT_LD + (lane >> 3) * 16;
      ldsm_x4(bk0, base);
      ldsm_x4(bk1, base + 64);
      mma_f16(sacc[j], qf[0], bk0[0], bk0[1]);
      mma_f16(sacc[j], qf[1], bk0[2], bk0[3]);
      mma_f16(sacc[j], qf[2], bk1[0], bk1[1]);
      mma_f16(sacc[j], qf[3], bk1[2], bk1[3]);
    }

    float tmx0 = -1e30f, tmx1 = -1e30f;
#pragma unroll
    for (int j = 0; j < 8; j++) {
      int kbase = kt + j * 8 + 2 * t;
      sacc[j][0] = (kbase     <= row0) ? sacc[j][0] * 0.125f : -1e30f;
      sacc[j][1] = (kbase + 1 <= row0) ? sacc[j][1] * 0.125f : -1e30f;
      sacc[j][2] = (kbase     <= row1) ? sacc[j][2] * 0.125f : -1e30f;
      sacc[j][3] = (kbase + 1 <= row1) ? sacc[j][3] * 0.125f : -1e30f;
      tmx0 = fmaxf(tmx0, fmaxf(sacc[j][0], sacc[j][1]));
      tmx1 = fmaxf(tmx1, fmaxf(sacc[j][2], sacc[j][3]));
    }
#pragma unroll
    for (int off = 1; off <= 2; off <<= 1) {
      tmx0 = fmaxf(tmx0, __shfl_xor_sync(0xffffffffu, tmx0, off));
      tmx1 = fmaxf(tmx1, __shfl_xor_sync(0xffffffffu, tmx1, off));
    }
    float mn0 = fmaxf(m0, tmx0), mn1 = fmaxf(m1, tmx1);
    float corr0 = __expf(m0 - mn0), corr1 = __expf(m1 - mn1);
    m0 = mn0; m1 = mn1;

    uint32_t pf[8][2];
    float sum0 = 0.f, sum1 = 0.f;
#pragma unroll
    for (int j = 0; j < 8; j++) {
      float p0 = __expf(sacc[j][0] - mn0);
      float p1 = __expf(sacc[j][1] - mn0);
      float p2 = __expf(sacc[j][2] - mn1);
      float p3 = __expf(sacc[j][3] - mn1);
      sum0 += p0 + p1; sum1 += p2 + p3;
      __half2 h01 = __floats2half2_rn(p0, p1);
      __half2 h23 = __floats2half2_rn(p2, p3);
      pf[j][0] = *reinterpret_cast<uint32_t*>(&h01);
      pf[j][1] = *reinterpret_cast<uint32_t*>(&h23);
    }
#pragma unroll
    for (int off = 1; off <= 2; off <<= 1) {
      sum0 += __shfl_xor_sync(0xffffffffu, sum0, off);
      sum1 += __shfl_xor_sync(0xffffffffu, sum1, off);
    }
    l0 = l0 * corr0 + sum0;
    l1 = l1 * corr1 + sum1;
#pragma unroll
    for (int np = 0; np < 8; np++) {
      oacc[np][0] *= corr0; oacc[np][1] *= corr0;
      oacc[np][2] *= corr1; oacc[np][3] *= corr1;
    }

#pragma unroll
    for (int kk = 0; kk < 4; kk++) {
      uint32_t a[4] = { pf[2 * kk][0], pf[2 * kk][1],
                        pf[2 * kk + 1][0], pf[2 * kk + 1][1] };
#pragma unroll
      for (int np = 0; np < 4; np++) {
        uint32_t r[4];
        ldsm_x4_t(r, vd + (uint32_t)(kk * 16 + (lane & 15)) * ATT_LD
                        + np * 32 + (lane >> 4) * 16);
        mma_f16(oacc[2 * np], a, r[0], r[1]);
        mma_f16(oacc[2 * np + 1], a, r[2], r[3]);
      }
    }
    __syncthreads();
  }

  const float inv0 = 1.0f / l0, inv1 = 1.0f / l1;
#pragma unroll
  for (int np = 0; np < 8; np++) {
    int col = h * D_HEAD + np * 8 + 2 * t;
    __half2 lo = __floats2half2_rn(oacc[np][0] * inv0, oacc[np][1] * inv0);
    __half2 hi = __floats2half2_rn(oacc[np][2] * inv1, oacc[np][3] * inv1);
    *reinterpret_cast<__half2*>(&z[(size_t)(b * S_LEN + row0) * D_MODEL + col]) = lo;
    *reinterpret_cast<__half2*>(&z[(size_t)(b * S_LEN + row1) * D_MODEL + col]) = hi;
  }
}

// -------------------- driver --------------------
template<bool GELU, bool ACCUM, bool OUTH, bool SWAP>
static void launch_hgemm(const __half* A, const __half* B, const float* bias,
                         void* C, int M, int K, int NB, int Nstore) {
  cudaFuncSetAttribute(hgemm<GELU, ACCUM, OUTH, SWAP>,
                       cudaFuncAttributeMaxDynamicSharedMemorySize, GEMM_SMEM);
  dim3 grid = SWAP ? dim3(M / 128, NB / 128) : dim3(NB / 128, M / 128);
  hgemm<GELU, ACCUM, OUTH, SWAP><<<grid, 256, GEMM_SMEM>>>(A, B, bias, C, M, K, NB, Nstore);
}

extern "C" void kernel_launch(void* const* d_in, const int* in_sizes, int n_in,
                              void* d_out, int out_size) {
  const int*   tokens = (const int*)  d_in[0];
  const float* W_E    = (const float*)d_in[1];
  const float* W_pos  = (const float*)d_in[2];
  const float* ln1_w  = (const float*)d_in[3];
  const float* ln1_b  = (const float*)d_in[4];
  const float* W_Q    = (const float*)d_in[5];
  const float* b_Q    = (const float*)d_in[6];
  const float* W_K    = (const float*)d_in[7];
  const float* b_K    = (const float*)d_in[8];
  const float* W_V    = (const float*)d_in[9];
  const float* b_V    = (const float*)d_in[10];
  const float* W_O    = (const float*)d_in[11];
  const float* b_O    = (const float*)d_in[12];
  const float* ln2_w  = (const float*)d_in[13];
  const float* ln2_b  = (const float*)d_in[14];
  const float* W_in   = (const float*)d_in[15];
  const float* b_in   = (const float*)d_in[16];
  const float* W_out  = (const float*)d_in[17];
  const float* b_out  = (const float*)d_in[18];
  const float* lnf_w  = (const float*)d_in[19];
  const float* lnf_b  = (const float*)d_in[20];
  const float* W_U    = (const float*)d_in[21];
  const float* b_U    = (const float*)d_in[22];
  float* out = (float*)d_out;

  float *resid, *bqkv;
  __half *xh, *qkvh, *zh, *hh, *wqkv, *wo, *win, *wout, *wu;
  cudaGetSymbolAddress((void**)&resid, g_resid);
  cudaGetSymbolAddress((void**)&xh,    g_xh);
  cudaGetSymbolAddress((void**)&qkvh,  g_qkvh);
  cudaGetSymbolAddress((void**)&zh,    g_zh);
  cudaGetSymbolAddress((void**)&hh,    g_hh);
  cudaGetSymbolAddress((void**)&wqkv,  g_wqkv);
  cudaGetSymbolAddress((void**)&bqkv,  g_bqkv);
  cudaGetSymbolAddress((void**)&wo,    g_wo);
  cudaGetSymbolAddress((void**)&win,   g_win);
  cudaGetSymbolAddress((void**)&wout,  g_wout);
  cudaGetSymbolAddress((void**)&wu,    g_wu);

  conv_qkv8<<<(N_LAYERS * D_MODEL * QKV_N) / 2048, 256>>>(W_Q, W_K, W_V, wqkv);
  pack_bias_qkv<<<(N_LAYERS * QKV_N) / 256, 256>>>(b_Q, b_K, b_V, bqkv);
  conv_flat8<<<(N_LAYERS * D_MODEL * D_MODEL) / 2048, 256>>>(W_O, wo);
  conv_flat8<<<(N_LAYERS * D_MODEL * D_MLP) / 2048, 256>>>(W_in, win);
  conv_flat8<<<(N_LAYERS * D_MLP * D_MODEL) / 2048, 256>>>(W_out, wout);
  {
    dim3 gv((N_VOCAB_PAD + 2047) / 2048, D_MODEL);
    conv_vocab8<<<gv, 256>>>(W_U, wu);
  }

  embed_kernel<<<N_TOKENS, 256>>>(tokens, W_E, W_pos, resid);

  dim3 gA(S_LEN / 64, N_HEADS, 2);

  for (int l = 0; l < N_LAYERS; l++) {
    size_t w1 = (size_t)l * D_MODEL * D_MODEL;
    size_t w2 = (size_t)l * D_MODEL * D_MLP;
    const float* l1w = ln1_w + (size_t)l * D_MODEL;
    const float* l1b = ln1_b + (size_t)l * D_MODEL;
    const float* l2w = ln2_w + (size_t)l * D_MODEL;
    const float* l2b = ln2_b + (size_t)l * D_MODEL;

    ln_kernel<<<N_TOKENS, 256>>>(resid, l1w, l1b, xh);
    launch_hgemm<false, false, true, false>(xh, wqkv + (size_t)l * D_MODEL * QKV_N,
                                            bqkv + (size_t)l * QKV_N, qkvh,
                                            N_TOKENS, D_MODEL, QKV_N, QKV_N);
    attn_tc<<<gA, 128>>>(qkvh, zh);
    launch_hgemm<false, true, false, false>(zh, wo + w1, b_O + (size_t)l * D_MODEL, resid,
                                            N_TOKENS, D_MODEL, D_MODEL, D_MODEL);
    ln_kernel<<<N_TOKENS, 256>>>(resid, l2w, l2b, xh);
    launch_hgemm<true, false, true, false>(xh, win + w2, b_in + (size_t)l * D_MLP, hh,
                                           N_TOKENS, D_MODEL, D_MLP, D_MLP);
    launch_hgemm<false, true, false, false>(hh, wout + w2, b_out + (size_t)l * D_MODEL, resid,
                                            N_TOKENS, D_MLP, D_MODEL, D_MODEL);
  }

  ln_kernel<<<N_TOKENS, 256>>>(resid, lnf_w, lnf_b, xh);
  // vocab GEMM: SWAP grid so B (103MB) is L2-reused instead of streamed 32x
  launch_hgemm<false, false, false, true>(xh, wu, b_U, out,
                                          N_TOKENS, D_MODEL, N_VOCAB_PAD, N_VOCAB);
}